// round 14
// baseline (speedup 1.0000x reference)
#include <cuda_runtime.h>
#include <cuda_fp16.h>
#include <cstdint>
#include <cstddef>

#define T_TOK 1024
#define HDIM  2048
#define IDIM  768
#define NEXP  64
#define TOPK  4
#define MT    64      // m-tile (tokens per expert tile)

// ---------------- static device scratch (no allocations) ----------------
__device__ int      g_counts[NEXP];
__device__ int      g_offs[NEXP];
__device__ int      g_cursor[NEXP];
__device__ int      g_topi[T_TOK * TOPK];
__device__ float    g_topw[T_TOK * TOPK];
__device__ int      g_tok[T_TOK * TOPK];
__device__ float    g_wt[T_TOK * TOPK];
__device__ int      g_slot[T_TOK * TOPK];
__device__ int      g_work[160];
__device__ int      g_nwork;
__device__ __half   g_Xh[(size_t)T_TOK * HDIM];          // fp16 X, pair-permuted (4 MB)
__device__ __half   g_Xg[(size_t)T_TOK * TOPK * HDIM];   // gathered per-slot X (16 MB)
__device__ __half   g_Yh[(size_t)T_TOK * TOPK * IDIM];   // fp16 Y, pair-permuted (6.3 MB)
__device__ float    g_Y2[(size_t)T_TOK * TOPK * HDIM];   // 33.6 MB

// ---------------- helpers ----------------
__device__ __forceinline__ uint32_t f2h2(float lo, float hi) {
    uint32_t r;
    asm("cvt.rn.f16x2.f32 %0, %1, %2;" : "=r"(r) : "f"(hi), "f"(lo));
    return r;
}
__device__ __forceinline__ void mma16(float* c, const uint32_t* a, const uint32_t* b) {
    asm volatile(
        "mma.sync.aligned.m16n8k16.row.col.f32.f16.f16.f32 "
        "{%0,%1,%2,%3}, {%4,%5,%6,%7}, {%8,%9}, {%0,%1,%2,%3};"
        : "+f"(c[0]), "+f"(c[1]), "+f"(c[2]), "+f"(c[3])
        : "r"(a[0]), "r"(a[1]), "r"(a[2]), "r"(a[3]), "r"(b[0]), "r"(b[1]));
}
__device__ __forceinline__ uint32_t smem_u32(const void* p) {
    uint32_t a;
    asm("{ .reg .u64 t; cvta.to.shared.u64 t, %1; cvt.u32.u64 %0, t; }"
        : "=r"(a) : "l"(p));
    return a;
}
// 1D bulk copy global->shared, mbarrier complete_tx (validated in R13)
__device__ __forceinline__ void bulk_g2s(uint32_t dst, const void* src,
                                         uint32_t bytes, uint32_t mbar) {
    asm volatile(
        "cp.async.bulk.shared::cluster.global.mbarrier::complete_tx::bytes "
        "[%0], [%1], %2, [%3];"
        :: "r"(dst), "l"(src), "r"(bytes), "r"(mbar) : "memory");
}
__device__ __forceinline__ void mbar_init(uint32_t mbar, uint32_t cnt) {
    asm volatile("mbarrier.init.shared.b64 [%0], %1;" :: "r"(mbar), "r"(cnt) : "memory");
}
__device__ __forceinline__ void mbar_expect_tx(uint32_t mbar, uint32_t bytes) {
    asm volatile("mbarrier.arrive.expect_tx.shared.b64 _, [%0], %1;"
                 :: "r"(mbar), "r"(bytes) : "memory");
}
__device__ __forceinline__ void mbar_wait(uint32_t mbar, uint32_t parity) {
    uint32_t done = 0;
    while (!done) {
        asm volatile(
            "{\n\t.reg .pred p;\n\t"
            "mbarrier.try_wait.parity.acquire.cta.shared::cta.b64 p, [%1], %2, 0x989680;\n\t"
            "selp.b32 %0, 1, 0, p;\n\t}"
            : "=r"(done) : "r"(mbar), "r"(parity) : "memory");
    }
}

// pair permutation in each 16-group: k -> (k&~15)|((k&7)>>1)<<2|((k>>3)&1)<<1|(k&1)

// ====== router: fp32 logits = X @ Gw^T + fused top-4; y=1 blocks: X->fp16
__global__ __launch_bounds__(256) void router_kernel(const float* __restrict__ x,
                                                     const float* __restrict__ gw) {
    const int tt = blockIdx.x;
    const int tid = threadIdx.x;

    if (blockIdx.y == 1) {
        for (int idx = tid; idx < 16 * (HDIM / 2); idx += 256) {
            int r = idx >> 10, k = (idx & (HDIM / 2 - 1)) * 2;
            const float* xr = x + (size_t)(tt * 16 + r) * HDIM;
            int p = (k & ~15) | (((k & 7) >> 1) << 2) | (((k >> 3) & 1) << 1);
            *(uint32_t*)&g_Xh[(size_t)(tt * 16 + r) * HDIM + p] = f2h2(xr[k], xr[k + 1]);
        }
        return;
    }

    __shared__ float Xs[16][72];
    __shared__ float Wt[64][72];
    const int t = tid & 15, eg = tid >> 4;
    float acc[4] = {0.f, 0.f, 0.f, 0.f};

    for (int kc = 0; kc < HDIM; kc += 64) {
        {
            int r = tid >> 4, q = tid & 15;
            float4 v = *(const float4*)(x + (size_t)(tt * 16 + r) * HDIM + kc + q * 4);
            *(float4*)&Xs[r][q * 4] = v;
        }
#pragma unroll
        for (int it = 0; it < 4; it++) {
            int s = it * 256 + tid;
            int e = s >> 4, q = s & 15;
            float4 v = *(const float4*)(gw + (size_t)e * HDIM + kc + q * 4);
            *(float4*)&Wt[e][q * 4] = v;
        }
        __syncthreads();
#pragma unroll
        for (int k = 0; k < 64; k += 4) {
            float4 a = *(const float4*)&Xs[t][k];
#pragma unroll
            for (int j = 0; j < 4; j++) {
                float4 b = *(const float4*)&Wt[eg * 4 + j][k];
                acc[j] += a.x * b.x + a.y * b.y + a.z * b.z + a.w * b.w;
            }
        }
        __syncthreads();
    }
#pragma unroll
    for (int j = 0; j < 4; j++) Wt[t][eg * 4 + j] = acc[j];
    __syncthreads();

    if (tid < 16) {
        float v0 = -1e30f, v1 = -1e30f, v2 = -1e30f, v3 = -1e30f;
        int i0 = 0, i1 = 0, i2 = 0, i3 = 0;
        for (int e = 0; e < NEXP; e++) {
            float l = Wt[tid][e];
            if (l > v3) {
                if (l > v2) {
                    v3 = v2; i3 = i2;
                    if (l > v1) {
                        v2 = v1; i2 = i1;
                        if (l > v0) { v1 = v0; i1 = i0; v0 = l; i0 = e; }
                        else        { v1 = l;  i1 = e; }
                    } else { v2 = l; i2 = e; }
                } else { v3 = l; i3 = e; }
            }
        }
        float e1 = expf(v1 - v0), e2 = expf(v2 - v0), e3 = expf(v3 - v0);
        float inv = 1.f / (1.f + e1 + e2 + e3);
        int   ii[4] = {i0, i1, i2, i3};
        float ww[4] = {inv, e1 * inv, e2 * inv, e3 * inv};
        int tok = tt * 16 + tid;
#pragma unroll
        for (int j = 0; j < TOPK; j++) {
            g_topi[tok * TOPK + j] = ii[j];
            g_topw[tok * TOPK + j] = ww[j];
            atomicAdd(&g_counts[ii[j]], 1);
        }
    }
}

// ------- scan + fill merged: one block, 1024 threads ----------------------
__global__ __launch_bounds__(1024) void scanfill_kernel() {
    __shared__ int cnt[NEXP], coff[NEXP], woff[NEXP];
    const int tid = threadIdx.x;
    if (tid < NEXP) cnt[tid] = g_counts[tid];
    __syncthreads();
    if (tid == 0) {
        int off = 0, w = 0;
        for (int i = 0; i < NEXP; i++) {
            coff[i] = off; off += cnt[i];
            woff[i] = w;   w += (cnt[i] + MT - 1) / MT;
        }
        g_nwork = w;
    }
    __syncthreads();
    if (tid < NEXP) {
        g_offs[tid] = coff[tid];
        g_cursor[tid] = 0;
        const int tiles = (cnt[tid] + MT - 1) / MT;
        for (int mt = 0; mt < tiles; mt++) g_work[woff[tid] + mt] = (tid << 6) | mt;
    }
    __syncthreads();
    const int t = tid;
#pragma unroll
    for (int j = 0; j < TOPK; j++) {
        int e = g_topi[t * TOPK + j];
        int p = atomicAdd(&g_cursor[e], 1);
        int idx = g_offs[e] + p;
        g_tok[idx] = t;
        g_wt[idx]  = g_topw[t * TOPK + j];
        g_slot[t * TOPK + j] = idx;
    }
}

// ------- gather: Xg[slot] = Xh[tok(slot)] (slot rows contiguous) ----------
__global__ __launch_bounds__(256) void gather_kernel() {
    const int slot = blockIdx.x * 4 + (threadIdx.x >> 6);
    const int l = threadIdx.x & 63;
    const uint4* src = (const uint4*)&g_Xh[(size_t)g_tok[slot] * HDIM];
    uint4* dst = (uint4*)&g_Xg[(size_t)slot * HDIM];
#pragma unroll
    for (int i = 0; i < 4; i++) dst[l + i * 64] = src[l + i * 64];
}

// SMEM layout (bytes), both GEMMs, 2 bulk stages, K-chunk 64, 1 CTA/SM:
//   mbar[2] @0..16
//   A stages: 2 x (64 rows x 224 B) @128     (fp16: 128 B data + pad; stride 112 halves)
//   B stages: 2 x (256 rows x 288 B) @28800  (fp32: 256 B data + pad; stride 72 floats)
#define KC      64
#define A_ROW   224
#define B_ROW   288
#define A_STG   (64 * A_ROW)        // 14336
#define B_STG   (256 * B_ROW)       // 73728
#define A0_OFF  128
#define B0_OFF  (128 + 2 * A_STG)   // 28800
#define G_SMEM  (B0_OFF + 2 * B_STG)            // 176256
#define TXB     (64u * 128u + 256u * 256u)      // 73728

// ====== GEMM1 (bulk): Yh = silu(Xg@Wg^T)*(Xg@Wu^T)*route_w ================
// 256 thr (8 warps), C tile m64 x (gate128 + up128); warp w: n16 gate + n16 up.
__global__ __launch_bounds__(256, 1) void gemm1_kernel(const float* __restrict__ gup) {
    extern __shared__ char smc[];
    const int widx = blockIdx.y;
    if (widx >= g_nwork) return;
    const int jt = blockIdx.x;                 // 0..5
    const int packed = g_work[widx];
    const int e = packed >> 6, mt = packed & 63;
    const int base = g_offs[e] + mt * MT;
    int m_cnt = g_counts[e] - mt * MT; if (m_cnt > MT) m_cnt = MT;

    const int tid = threadIdx.x;
    const int w = tid >> 5, lane = tid & 31;
    const int lr = lane >> 2, lc = lane & 3;
    const uint32_t smb = smem_u32(smc);

    if (tid == 0) { mbar_init(smb, 1); mbar_init(smb + 8, 1); }
    __syncthreads();
    if (tid == 0) { mbar_expect_tx(smb, TXB); mbar_expect_tx(smb + 8, TXB); }
    __syncthreads();

    // bulk row assignments: every thread owns B row tid; threads <64 also A row tid
    const float* bwsrc;
    {
        int r = tid;
        int jrow = (r < 128) ? (jt * 128 + r) : (IDIM + jt * 128 + (r - 128));
        bwsrc = gup + (size_t)e * (2 * IDIM) * HDIM + (size_t)jrow * HDIM;
    }
    const uint32_t bdst = smb + B0_OFF + tid * B_ROW;
    const __half* axsrc = nullptr;
    uint32_t adst = 0;
    if (tid < 64) {
        int slot = base + tid; if (slot > T_TOK * TOPK - 1) slot = T_TOK * TOPK - 1;
        axsrc = &g_Xg[(size_t)slot * HDIM];
        adst = smb + A0_OFF + tid * A_ROW;
    }

    const int NC = HDIM / KC;   // 32
    // prologue: chunks 0,1 -> stages 0,1
#pragma unroll
    for (int p = 0; p < 2; p++) {
        bulk_g2s(bdst + p * B_STG, bwsrc + p * KC, KC * 4, smb + 8 * p);
        if (tid < 64)
            bulk_g2s(adst + p * A_STG, axsrc + p * KC, KC * 2, smb + 8 * p);
    }

    float cg[4][2][4], cu[4][2][4];
#pragma unroll
    for (int a = 0; a < 4; a++)
#pragma unroll
        for (int b = 0; b < 2; b++)
#pragma unroll
            for (int c = 0; c < 4; c++) { cg[a][b][c] = 0.f; cu[a][b][c] = 0.f; }

    for (int ck = 0; ck < NC; ck++) {
        const int s = ck & 1;
        mbar_wait(smb + 8 * s, (uint32_t)((ck >> 1) & 1));
        if (tid == 0 && ck + 2 < NC) mbar_expect_tx(smb + 8 * s, TXB);

        const __half* Ast = (const __half*)(smc + A0_OFF + s * A_STG);
        const float*  Bst = (const float*)(smc + B0_OFF + s * B_STG);
#pragma unroll
        for (int kki = 0; kki < 4; kki++) {
            const int kk = kki * 16;
            uint32_t a[4][4];
#pragma unroll
            for (int mi = 0; mi < 4; mi++) {
                uint2 lo = *(const uint2*)(Ast + (mi * 16 + lr) * 112 + kk + 4 * lc);
                uint2 hi = *(const uint2*)(Ast + (mi * 16 + 8 + lr) * 112 + kk + 4 * lc);
                a[mi][0] = lo.x; a[mi][1] = hi.x; a[mi][2] = lo.y; a[mi][3] = hi.y;
            }
            uint32_t bg[2][2], bu[2][2];
#pragma unroll
            for (int ni = 0; ni < 2; ni++) {
                int nr = w * 16 + ni * 8 + lr;
                float2 p0 = *(const float2*)(Bst + nr * 72 + kk + 2 * lc);
                float2 p1 = *(const float2*)(Bst + nr * 72 + kk + 2 * lc + 8);
                bg[ni][0] = f2h2(p0.x, p0.y); bg[ni][1] = f2h2(p1.x, p1.y);
                float2 q0 = *(const float2*)(Bst + (128 + nr) * 72 + kk + 2 * lc);
                float2 q1 = *(const float2*)(Bst + (128 + nr) * 72 + kk + 2 * lc + 8);
                bu[ni][0] = f2h2(q0.x, q0.y); bu[ni][1] = f2h2(q1.x, q1.y);
            }
#pragma unroll
            for (int mi = 0; mi < 4; mi++)
#pragma unroll
                for (int ni = 0; ni < 2; ni++) {
                    mma16(cg[mi][ni], a[mi], bg[ni]);
                    mma16(cu[mi][ni], a[mi], bu[ni]);
                }
        }
        __syncthreads();
        const int nk = ck + 2;
        if (nk < NC) {
            bulk_g2s(bdst + s * B_STG, bwsrc + (size_t)nk * KC, KC * 4, smb + 8 * s);
            if (tid < 64)
                bulk_g2s(adst + s * A_STG, axsrc + (size_t)nk * KC, KC * 2, smb + 8 * s);
        }
    }

    // epilogue: silu(g)*u*route_w -> Yh (fp16, pair-permuted)
#pragma unroll
    for (int ni = 0; ni < 2; ni++) {
        const int n0 = jt * 128 + w * 16 + ni * 8 + 2 * lc;   // even
        const int p = (n0 & ~15) | (((n0 & 7) >> 1) << 2) | (((n0 >> 3) & 1) << 1);
#pragma unroll
        for (int mi = 0; mi < 4; mi++)
#pragma unroll
            for (int h = 0; h < 2; h++) {
                int row = mi * 16 + lr + h * 8;
                if (row < m_cnt) {
                    float wt = g_wt[base + row];
                    float g0 = cg[mi][ni][h * 2],     g1 = cg[mi][ni][h * 2 + 1];
                    float u0 = cu[mi][ni][h * 2],     u1 = cu[mi][ni][h * 2 + 1];
                    float y0 = g0 / (1.f + __expf(-g0)) * u0 * wt;
                    float y1 = g1 / (1.f + __expf(-g1)) * u1 * wt;
                    *(uint32_t*)&g_Yh[(size_t)(base + row) * IDIM + p] = f2h2(y0, y1);
                }
            }
    }
}

// ====== GEMM2 (bulk): Y2 = Yh @ W2^T, m64 x n256, K=768 (12 chunks) =======
__global__ __launch_bounds__(256, 1) void gemm2_kernel(const float* __restrict__ down) {
    extern __shared__ char smc[];
    const int widx = blockIdx.y;
    if (widx >= g_nwork) return;
    const int ht = blockIdx.x;                 // 0..7
    const int packed = g_work[widx];
    const int e = packed >> 6, mt = packed & 63;
    const int base = g_offs[e] + mt * MT;
    int m_cnt = g_counts[e] - mt * MT; if (m_cnt > MT) m_cnt = MT;

    const int tid = threadIdx.x;
    const int w = tid >> 5, lane = tid & 31;
    const int lr = lane >> 2, lc = lane & 3;
    const uint32_t smb = smem_u32(smc);

    if (tid == 0) { mbar_init(smb, 1); mbar_init(smb + 8, 1); }
    __syncthreads();
    if (tid == 0) { mbar_expect_tx(smb, TXB); mbar_expect_tx(smb + 8, TXB); }
    __syncthreads();

    const float* bwsrc = down + (size_t)e * HDIM * IDIM + (size_t)(ht * 256 + tid) * IDIM;
    const uint32_t bdst = smb + B0_OFF + tid * B_ROW;
    const __half* aysrc = nullptr;
    uint32_t adst = 0;
    if (tid < 64) {
        int slot = base + tid; if (slot > T_TOK * TOPK - 1) slot = T_TOK * TOPK - 1;
        aysrc = &g_Yh[(size_t)slot * IDIM];
        adst = smb + A0_OFF + tid * A_ROW;
    }

    const int NC = IDIM / KC;   // 12
#pragma unroll
    for (int p = 0; p < 2; p++) {
        bulk_g2s(bdst + p * B_STG, bwsrc + p * KC, KC * 4, smb + 8 * p);
        if (tid < 64)
            bulk_g2s(adst + p * A_STG, aysrc + p * KC, KC * 2, smb + 8 * p);
    }

    float c[4][4][4];
#pragma unroll
    for (int a = 0; a < 4; a++)
#pragma unroll
        for (int b = 0; b < 4; b++)
#pragma unroll
            for (int k = 0; k < 4; k++) c[a][b][k] = 0.f;

    for (int ck = 0; ck < NC; ck++) {
        const int s = ck & 1;
        mbar_wait(smb + 8 * s, (uint32_t)((ck >> 1) & 1));
        if (tid == 0 && ck + 2 < NC) mbar_expect_tx(smb + 8 * s, TXB);

        const __half* Ast = (const __half*)(smc + A0_OFF + s * A_STG);
        const float*  Bst = (const float*)(smc + B0_OFF + s * B_STG);
#pragma unroll
        for (int kki = 0; kki < 4; kki++) {
            const int kk = kki * 16;
            uint32_t a[4][4];
#pragma unroll
            for (int mi = 0; mi < 4; mi++) {
                uint2 lo = *(const uint2*)(Ast + (mi * 16 + lr) * 112 + kk + 4 * lc);
                uint2 hi = *(const uint2*)(Ast + (mi * 16 + 8 + lr) * 112 + kk + 4 * lc);
                a[mi][0] = lo.x; a[mi][1] = hi.x; a[mi][2] = lo.y; a[mi][3] = hi.y;
            }
            uint32_t b[4][2];
#pragma unroll
            for (int ni = 0; ni < 4; ni++) {
                int nr = w * 32 + ni * 8 + lr;
                float2 p0 = *(const float2*)(Bst + nr * 72 + kk + 2 * lc);
                float2 p1 = *(const float2*)(Bst + nr * 72 + kk + 2 * lc + 8);
                b[ni][0] = f2h2(p0.x, p0.y); b[ni][1] = f2h2(p1.x, p1.y);
            }
#pragma unroll
            for (int mi = 0; mi < 4; mi++)
#pragma unroll
                for (int ni = 0; ni < 4; ni++) mma16(c[mi][ni], a[mi], b[ni]);
        }
        __syncthreads();
        const int nk = ck + 2;
        if (nk < NC) {
            bulk_g2s(bdst + s * B_STG, bwsrc + (size_t)nk * KC, KC * 4, smb + 8 * s);
            if (tid < 64)
                bulk_g2s(adst + s * A_STG, aysrc + (size_t)nk * KC, KC * 2, smb + 8 * s);
        }
    }

#pragma unroll
    for (int mi = 0; mi < 4; mi++)
#pragma unroll
        for (int ni = 0; ni < 4; ni++) {
            int col = ht * 256 + w * 32 + ni * 8 + 2 * lc;
#pragma unroll
            for (int h = 0; h < 2; h++) {
                int row = mi * 16 + lr + h * 8;
                if (row < m_cnt) {
                    *(float2*)&g_Y2[(size_t)(base + row) * HDIM + col] =
                        make_float2(c[mi][ni][h * 2], c[mi][ni][h * 2 + 1]);
                }
            }
        }
}

// ------ combine: out[t] = sum of token's 4 slots; re-zero counts ----------
__global__ __launch_bounds__(256) void combine_kernel(float* __restrict__ out) {
    const int t = blockIdx.x;
    const int tid = threadIdx.x;
    if (t == 0 && tid < NEXP) g_counts[tid] = 0;
    const int s0 = g_slot[t * TOPK + 0], s1 = g_slot[t * TOPK + 1];
    const int s2 = g_slot[t * TOPK + 2], s3 = g_slot[t * TOPK + 3];
    const float* y0 = &g_Y2[(size_t)s0 * HDIM];
    const float* y1 = &g_Y2[(size_t)s1 * HDIM];
    const float* y2 = &g_Y2[(size_t)s2 * HDIM];
    const float* y3 = &g_Y2[(size_t)s3 * HDIM];
#pragma unroll
    for (int i = 0; i < 2; i++) {
        int h = (tid + i * 256) * 4;
        float4 a = *(const float4*)(y0 + h);
        float4 b = *(const float4*)(y1 + h);
        float4 cc = *(const float4*)(y2 + h);
        float4 d = *(const float4*)(y3 + h);
        float4 r;
        r.x = a.x + b.x + cc.x + d.x;
        r.y = a.y + b.y + cc.y + d.y;
        r.z = a.z + b.z + cc.z + d.z;
        r.w = a.w + b.w + cc.w + d.w;
        *(float4*)(out + (size_t)t * HDIM + h) = r;
    }
}

// ---------------- launch ----------------
extern "C" void kernel_launch(void* const* d_in, const int* in_sizes, int n_in,
                              void* d_out, int out_size) {
    const float* x    = (const float*)d_in[0];   // [1,1024,2048]
    const float* gw   = (const float*)d_in[1];   // [64,2048]
    const float* gup  = (const float*)d_in[2];   // [64,1536,2048]
    const float* down = (const float*)d_in[3];   // [64,2048,768]
    float* out = (float*)d_out;

    cudaFuncSetAttribute(gemm1_kernel, cudaFuncAttributeMaxDynamicSharedMemorySize, G_SMEM);
    cudaFuncSetAttribute(gemm2_kernel, cudaFuncAttributeMaxDynamicSharedMemorySize, G_SMEM);

    router_kernel<<<dim3(64, 2), 256>>>(x, gw);          // launch 0
    scanfill_kernel<<<1, 1024>>>();                      // launch 1
    gather_kernel<<<1024, 256>>>();                      // launch 2
    gemm1_kernel<<<dim3(6, 128), 256, G_SMEM>>>(gup);    // launch 3 (ncu target)
    gemm2_kernel<<<dim3(8, 128), 256, G_SMEM>>>(down);   // launch 4
    combine_kernel<<<1024, 256>>>(out);                  // launch 5
}

// round 15
// speedup vs baseline: 1.5141x; 1.5141x over previous
#include <cuda_runtime.h>
#include <cuda_fp16.h>
#include <cstdint>
#include <cstddef>

#define T_TOK 1024
#define HDIM  2048
#define IDIM  768
#define NEXP  64
#define TOPK  4
#define MT    64      // m-tile (tokens per expert tile)

// ---------------- static device scratch (no allocations) ----------------
__device__ int      g_counts[NEXP];      // incremented by router/topk, zeroed by scan
__device__ int      g_cnt2[NEXP];        // snapshot used by GEMMs
__device__ int      g_offs[NEXP];
__device__ int      g_cursor[NEXP];
__device__ int      g_topi[T_TOK * TOPK];
__device__ float    g_topw[T_TOK * TOPK];
__device__ int      g_tok[T_TOK * TOPK];
__device__ float    g_wt[T_TOK * TOPK];
__device__ int      g_work[160];
__device__ int      g_nwork;
__device__ __half   g_Xh[(size_t)T_TOK * HDIM];          // fp16 X, pair-permuted
__device__ __half   g_Yh[(size_t)T_TOK * TOPK * IDIM];   // fp16 Y, pair-permuted

// ---------------- helpers ----------------
__device__ __forceinline__ uint32_t f2h2(float lo, float hi) {
    uint32_t r;
    asm("cvt.rn.f16x2.f32 %0, %1, %2;" : "=r"(r) : "f"(hi), "f"(lo));
    return r;
}
__device__ __forceinline__ void mma16(float* c, const uint32_t* a, const uint32_t* b) {
    asm volatile(
        "mma.sync.aligned.m16n8k16.row.col.f32.f16.f16.f32 "
        "{%0,%1,%2,%3}, {%4,%5,%6,%7}, {%8,%9}, {%0,%1,%2,%3};"
        : "+f"(c[0]), "+f"(c[1]), "+f"(c[2]), "+f"(c[3])
        : "r"(a[0]), "r"(a[1]), "r"(a[2]), "r"(a[3]), "r"(b[0]), "r"(b[1]));
}
__device__ __forceinline__ void cp16(uint32_t dst_smem, const void* src) {
    asm volatile("cp.async.cg.shared.global [%0], [%1], 16;"
                 :: "r"(dst_smem), "l"(src));
}
__device__ __forceinline__ uint32_t smem_u32(const void* p) {
    uint32_t a;
    asm("{ .reg .u64 t; cvta.to.shared.u64 t, %1; cvt.u32.u64 %0, t; }"
        : "=r"(a) : "l"(p));
    return a;
}
#define CP_COMMIT()  asm volatile("cp.async.commit_group;")
#define CP_WAIT1()   asm volatile("cp.async.wait_group 1;")

// pair permutation in each 16-group: k -> (k&~15)|((k&7)>>1)<<2|((k>>3)&1)<<1|(k&1)

// ====== router: fp32 logits = X @ Gw^T + fused top-4; y=1: X->fp16 + zero out
__global__ __launch_bounds__(256) void router_kernel(const float* __restrict__ x,
                                                     const float* __restrict__ gw,
                                                     float* __restrict__ out) {
    const int tt = blockIdx.x;
    const int tid = threadIdx.x;

    if (blockIdx.y == 1) {
        // zero this tile's 16 output rows (out poisoned by harness each run)
        float4 z = make_float4(0.f, 0.f, 0.f, 0.f);
        float4* o4 = (float4*)(out + (size_t)tt * 16 * HDIM);
        for (int i = tid; i < 16 * HDIM / 4; i += 256) o4[i] = z;
        // X convert: fp16 + pair-permute
        for (int idx = tid; idx < 16 * (HDIM / 2); idx += 256) {
            int r = idx >> 10, k = (idx & (HDIM / 2 - 1)) * 2;
            const float* xr = x + (size_t)(tt * 16 + r) * HDIM;
            int p = (k & ~15) | (((k & 7) >> 1) << 2) | (((k >> 3) & 1) << 1);
            *(uint32_t*)&g_Xh[(size_t)(tt * 16 + r) * HDIM + p] = f2h2(xr[k], xr[k + 1]);
        }
        return;
    }

    __shared__ float Xs[16][72];
    __shared__ float Wt[64][72];
    const int t = tid & 15, eg = tid >> 4;
    float acc[4] = {0.f, 0.f, 0.f, 0.f};

    for (int kc = 0; kc < HDIM; kc += 64) {
        {
            int r = tid >> 4, q = tid & 15;
            float4 v = *(const float4*)(x + (size_t)(tt * 16 + r) * HDIM + kc + q * 4);
            *(float4*)&Xs[r][q * 4] = v;
        }
#pragma unroll
        for (int it = 0; it < 4; it++) {
            int s = it * 256 + tid;
            int e = s >> 4, q = s & 15;
            float4 v = *(const float4*)(gw + (size_t)e * HDIM + kc + q * 4);
            *(float4*)&Wt[e][q * 4] = v;
        }
        __syncthreads();
#pragma unroll
        for (int k = 0; k < 64; k += 4) {
            float4 a = *(const float4*)&Xs[t][k];
#pragma unroll
            for (int j = 0; j < 4; j++) {
                float4 b = *(const float4*)&Wt[eg * 4 + j][k];
                acc[j] += a.x * b.x + a.y * b.y + a.z * b.z + a.w * b.w;
            }
        }
        __syncthreads();
    }
#pragma unroll
    for (int j = 0; j < 4; j++) Wt[t][eg * 4 + j] = acc[j];
    __syncthreads();

    if (tid < 16) {
        float v0 = -1e30f, v1 = -1e30f, v2 = -1e30f, v3 = -1e30f;
        int i0 = 0, i1 = 0, i2 = 0, i3 = 0;
        for (int e = 0; e < NEXP; e++) {
            float l = Wt[tid][e];
            if (l > v3) {
                if (l > v2) {
                    v3 = v2; i3 = i2;
                    if (l > v1) {
                        v2 = v1; i2 = i1;
                        if (l > v0) { v1 = v0; i1 = i0; v0 = l; i0 = e; }
                        else        { v1 = l;  i1 = e; }
                    } else { v2 = l; i2 = e; }
                } else { v3 = l; i3 = e; }
            }
        }
        float e1 = expf(v1 - v0), e2 = expf(v2 - v0), e3 = expf(v3 - v0);
        float inv = 1.f / (1.f + e1 + e2 + e3);
        int   ii[4] = {i0, i1, i2, i3};
        float ww[4] = {inv, e1 * inv, e2 * inv, e3 * inv};
        int tok = tt * 16 + tid;
#pragma unroll
        for (int j = 0; j < TOPK; j++) {
            g_topi[tok * TOPK + j] = ii[j];
            g_topw[tok * TOPK + j] = ww[j];
            atomicAdd(&g_counts[ii[j]], 1);
        }
    }
}

// ------- scan: snapshot counts, offsets, work list; re-zero g_counts -------
__global__ __launch_bounds__(256) void scan_kernel() {
    __shared__ int cnt[NEXP], coff[NEXP], woff[NEXP];
    const int tid = threadIdx.x;
    if (tid < NEXP) {
        cnt[tid] = g_counts[tid];
        g_cnt2[tid] = cnt[tid];
        g_counts[tid] = 0;           // ready for next call
    }
    __syncthreads();
    if (tid == 0) {
        int off = 0, w = 0;
        for (int i = 0; i < NEXP; i++) {
            coff[i] = off; off += cnt[i];
            woff[i] = w;   w += (cnt[i] + MT - 1) / MT;
        }
        g_nwork = w;
    }
    __syncthreads();
    if (tid < NEXP) {
        g_offs[tid] = coff[tid];
        g_cursor[tid] = 0;
        const int tiles = (cnt[tid] + MT - 1) / MT;
        for (int mt = 0; mt < tiles; mt++) g_work[woff[tid] + mt] = (tid << 6) | mt;
    }
}

// ------- fill compact per-expert token/weight lists ------------------------
__global__ __launch_bounds__(256) void fill_kernel() {
    const int t = blockIdx.x * 256 + threadIdx.x;
    if (t >= T_TOK) return;
#pragma unroll
    for (int j = 0; j < TOPK; j++) {
        int e = g_topi[t * TOPK + j];
        int p = atomicAdd(&g_cursor[e], 1);
        int idx = g_offs[e] + p;
        g_tok[idx] = t;
        g_wt[idx]  = g_topw[t * TOPK + j];
    }
}

// SMEM layout (bytes), both GEMMs, 2-stage, sized for 2 CTAs/SM:
//   A stages: 2 x (64 rows x 96 B)   = [0, 12288)   (fp16, stride 48 halves)
//   B stages: 2 x (256 rows x 160 B) = [12288, 94208)  (fp32, stride 40 floats)
//   s_tok @94208 (256 B), s_wt @94464 (256 B)
#define A_ST_B  6144
#define B_ST_B  40960
#define B_BASE  12288
#define TOK_B   94208
#define G_SMEM  94976

// ====== GEMM1: Yh[slot] = silu(Xh@Wg^T) * (Xh@Wu^T) * route_w, fp16 =======
// 256 thr (8 warps), 2 CTAs/SM. C tile m64 x (gate128 + up128); warp: n16+n16.
__global__ __launch_bounds__(256, 2) void gemm1_kernel(const float* __restrict__ gup) {
    extern __shared__ char smc[];
    const int widx = blockIdx.y;
    if (widx >= g_nwork) return;
    const int jt = blockIdx.x;                 // 0..5
    const int packed = g_work[widx];
    const int e = packed >> 6, mt = packed & 63;
    const int base = g_offs[e] + mt * MT;
    int m_cnt = g_cnt2[e] - mt * MT; if (m_cnt > MT) m_cnt = MT;

    int*   s_tok = (int*)(smc + TOK_B);
    float* s_wt  = (float*)(smc + TOK_B + 256);
    const int tid = threadIdx.x;
    const int w = tid >> 5, lane = tid & 31;
    const int lr = lane >> 2, lc = lane & 3;
    const uint32_t smb = smem_u32(smc);

    if (tid < 64) {
        int tk = 0; float wt = 0.f;
        if (tid < m_cnt) { tk = g_tok[base + tid]; wt = g_wt[base + tid]; }
        s_tok[tid] = tk; s_wt[tid] = wt;
    }
    __syncthreads();

    // cp.async: A (fp16): thread -> row tid>>2, 16B group tid&3
    const int arow = tid >> 2, ag = tid & 3;
    const __half* xsrc = &g_Xh[(size_t)s_tok[arow] * HDIM + ag * 8];
    const uint32_t adst = smb + arow * 96 + ag * 16;
    // B (fp32): 8 chunks of rows
    const float* bsrc[8]; uint32_t bdst[8];
#pragma unroll
    for (int i = 0; i < 8; i++) {
        int r = (tid >> 3) + 32 * i, q = tid & 7;
        int jrow = (r < 128) ? (jt * 128 + r) : (IDIM + jt * 128 + (r - 128));
        bsrc[i] = gup + (size_t)e * (2 * IDIM) * HDIM + (size_t)jrow * HDIM + q * 4;
        bdst[i] = smb + B_BASE + r * 160 + q * 16;
    }

    float cg[4][2][4], cu[4][2][4];
#pragma unroll
    for (int a = 0; a < 4; a++)
#pragma unroll
        for (int b = 0; b < 2; b++)
#pragma unroll
            for (int c = 0; c < 4; c++) { cg[a][b][c] = 0.f; cu[a][b][c] = 0.f; }

    const int NC = HDIM / 32;   // 64 chunks
#pragma unroll
    for (int p = 0; p < 2; p++) {
        cp16(adst + p * A_ST_B, xsrc + p * 32);
#pragma unroll
        for (int i = 0; i < 8; i++) cp16(bdst[i] + p * B_ST_B, bsrc[i] + p * 32);
        CP_COMMIT();
    }

    for (int ck = 0; ck < NC; ck++) {
        CP_WAIT1();
        __syncthreads();
        const int st = ck & 1;
        const __half* Ast = (const __half*)(smc + st * A_ST_B);
        const float*  Bst = (const float*)(smc + B_BASE + st * B_ST_B);
#pragma unroll
        for (int kki = 0; kki < 2; kki++) {
            const int kk = kki * 16;
            uint32_t a[4][4];
#pragma unroll
            for (int mi = 0; mi < 4; mi++) {
                uint2 lo = *(const uint2*)(Ast + (mi * 16 + lr) * 48 + kk + 4 * lc);
                uint2 hi = *(const uint2*)(Ast + (mi * 16 + 8 + lr) * 48 + kk + 4 * lc);
                a[mi][0] = lo.x; a[mi][1] = hi.x; a[mi][2] = lo.y; a[mi][3] = hi.y;
            }
            uint32_t bg[2][2], bu[2][2];
#pragma unroll
            for (int ni = 0; ni < 2; ni++) {
                int nr = w * 16 + ni * 8 + lr;
                float2 p0 = *(const float2*)(Bst + nr * 40 + kk + 2 * lc);
                float2 p1 = *(const float2*)(Bst + nr * 40 + kk + 2 * lc + 8);
                bg[ni][0] = f2h2(p0.x, p0.y); bg[ni][1] = f2h2(p1.x, p1.y);
                float2 q0 = *(const float2*)(Bst + (128 + nr) * 40 + kk + 2 * lc);
                float2 q1 = *(const float2*)(Bst + (128 + nr) * 40 + kk + 2 * lc + 8);
                bu[ni][0] = f2h2(q0.x, q0.y); bu[ni][1] = f2h2(q1.x, q1.y);
            }
#pragma unroll
            for (int mi = 0; mi < 4; mi++)
#pragma unroll
                for (int ni = 0; ni < 2; ni++) {
                    mma16(cg[mi][ni], a[mi], bg[ni]);
                    mma16(cu[mi][ni], a[mi], bu[ni]);
                }
        }
        __syncthreads();
        const int nk = ck + 2;
        if (nk < NC) {
            const int kc = nk * 32;
            const uint32_t so = (nk & 1) ? A_ST_B : 0;
            const uint32_t bo = (nk & 1) ? B_ST_B : 0;
            cp16(adst + so, xsrc + kc);
#pragma unroll
            for (int i = 0; i < 8; i++) cp16(bdst[i] + bo, bsrc[i] + kc);
        }
        CP_COMMIT();
    }

    // epilogue: silu(g)*u*route_w -> Yh (fp16, pair-permuted)
#pragma unroll
    for (int mi = 0; mi < 4; mi++)
#pragma unroll
        for (int ni = 0; ni < 2; ni++) {
            const int n0 = jt * 128 + w * 16 + ni * 8 + 2 * lc;   // even
            const int p = (n0 & ~15) | (((n0 & 7) >> 1) << 2) | (((n0 >> 3) & 1) << 1);
#pragma unroll
            for (int h = 0; h < 2; h++) {
                int row = mi * 16 + lr + h * 8;
                if (row < m_cnt) {
                    float wt = s_wt[row];
                    float g0 = cg[mi][ni][h * 2],     g1 = cg[mi][ni][h * 2 + 1];
                    float u0 = cu[mi][ni][h * 2],     u1 = cu[mi][ni][h * 2 + 1];
                    float y0 = g0 / (1.f + __expf(-g0)) * u0 * wt;
                    float y1 = g1 / (1.f + __expf(-g1)) * u1 * wt;
                    *(uint32_t*)&g_Yh[(size_t)(base + row) * IDIM + p] = f2h2(y0, y1);
                }
            }
        }
}

// ====== GEMM2: out[token] += Yh @ W2^T (atomic combine), m64 x n256 =======
__global__ __launch_bounds__(256, 2) void gemm2_kernel(const float* __restrict__ down,
                                                       float* __restrict__ out) {
    extern __shared__ char smc[];
    const int widx = blockIdx.y;
    if (widx >= g_nwork) return;
    const int ht = blockIdx.x;                 // 0..7
    const int packed = g_work[widx];
    const int e = packed >> 6, mt = packed & 63;
    const int base = g_offs[e] + mt * MT;
    int m_cnt = g_cnt2[e] - mt * MT; if (m_cnt > MT) m_cnt = MT;

    const int tid = threadIdx.x;
    const int w = tid >> 5, lane = tid & 31;
    const int lr = lane >> 2, lc = lane & 3;
    const uint32_t smb = smem_u32(smc);

    const int arow = tid >> 2, ag = tid & 3;
    int slot = base + arow; if (slot > T_TOK * TOPK - 1) slot = T_TOK * TOPK - 1;
    const __half* ysrc = &g_Yh[(size_t)slot * IDIM + ag * 8];
    const uint32_t adst = smb + arow * 96 + ag * 16;
    const float* bsrc[8]; uint32_t bdst[8];
#pragma unroll
    for (int i = 0; i < 8; i++) {
        int r = (tid >> 3) + 32 * i, q = tid & 7;
        bsrc[i] = down + (size_t)e * HDIM * IDIM + (size_t)(ht * 256 + r) * IDIM + q * 4;
        bdst[i] = smb + B_BASE + r * 160 + q * 16;
    }

    float c[4][4][4];
#pragma unroll
    for (int a = 0; a < 4; a++)
#pragma unroll
        for (int b = 0; b < 4; b++)
#pragma unroll
            for (int k = 0; k < 4; k++) c[a][b][k] = 0.f;

    const int NC = IDIM / 32;   // 24 chunks
#pragma unroll
    for (int p = 0; p < 2; p++) {
        cp16(adst + p * A_ST_B, ysrc + p * 32);
#pragma unroll
        for (int i = 0; i < 8; i++) cp16(bdst[i] + p * B_ST_B, bsrc[i] + p * 32);
        CP_COMMIT();
    }

    for (int ck = 0; ck < NC; ck++) {
        CP_WAIT1();
        __syncthreads();
        const int st = ck & 1;
        const __half* Ast = (const __half*)(smc + st * A_ST_B);
        const float*  Bst = (const float*)(smc + B_BASE + st * B_ST_B);
#pragma unroll
        for (int kki = 0; kki < 2; kki++) {
            const int kk = kki * 16;
            uint32_t a[4][4];
#pragma unroll
            for (int mi = 0; mi < 4; mi++) {
                uint2 lo = *(const uint2*)(Ast + (mi * 16 + lr) * 48 + kk + 4 * lc);
                uint2 hi = *(const uint2*)(Ast + (mi * 16 + 8 + lr) * 48 + kk + 4 * lc);
                a[mi][0] = lo.x; a[mi][1] = hi.x; a[mi][2] = lo.y; a[mi][3] = hi.y;
            }
            uint32_t b[4][2];
#pragma unroll
            for (int ni = 0; ni < 4; ni++) {
                int nr = w * 32 + ni * 8 + lr;
                float2 p0 = *(const float2*)(Bst + nr * 40 + kk + 2 * lc);
                float2 p1 = *(const float2*)(Bst + nr * 40 + kk + 2 * lc + 8);
                b[ni][0] = f2h2(p0.x, p0.y); b[ni][1] = f2h2(p1.x, p1.y);
            }
#pragma unroll
            for (int mi = 0; mi < 4; mi++)
#pragma unroll
                for (int ni = 0; ni < 4; ni++) mma16(c[mi][ni], a[mi], b[ni]);
        }
        __syncthreads();
        const int nk = ck + 2;
        if (nk < NC) {
            const int kc = nk * 32;
            const uint32_t so = (nk & 1) ? A_ST_B : 0;
            const uint32_t bo = (nk & 1) ? B_ST_B : 0;
            cp16(adst + so, ysrc + kc);
#pragma unroll
            for (int i = 0; i < 8; i++) cp16(bdst[i] + bo, bsrc[i] + kc);
        }
        CP_COMMIT();
    }

    // epilogue: atomic accumulate into out[token] (combines the 4 experts)
#pragma unroll
    for (int mi = 0; mi < 4; mi++) {
        int tok_h[2]; bool act[2];
#pragma unroll
        for (int h = 0; h < 2; h++) {
            int row = mi * 16 + lr + h * 8;
            act[h] = row < m_cnt;
            tok_h[h] = act[h] ? g_tok[base + row] : 0;
        }
#pragma unroll
        for (int ni = 0; ni < 4; ni++) {
            int col = ht * 256 + w * 32 + ni * 8 + 2 * lc;
#pragma unroll
            for (int h = 0; h < 2; h++) {
                if (act[h]) {
                    float* o = out + (size_t)tok_h[h] * HDIM + col;
                    atomicAdd(o,     c[mi][ni][h * 2]);
                    atomicAdd(o + 1, c[mi][ni][h * 2 + 1]);
                }
            }
        }
    }
}

// ---------------- launch ----------------
extern "C" void kernel_launch(void* const* d_in, const int* in_sizes, int n_in,
                              void* d_out, int out_size) {
    const float* x    = (const float*)d_in[0];   // [1,1024,2048]
    const float* gw   = (const float*)d_in[1];   // [64,2048]
    const float* gup  = (const float*)d_in[2];   // [64,1536,2048]
    const float* down = (const float*)d_in[3];   // [64,2048,768]
    float* out = (float*)d_out;

    cudaFuncSetAttribute(gemm1_kernel, cudaFuncAttributeMaxDynamicSharedMemorySize, G_SMEM);
    cudaFuncSetAttribute(gemm2_kernel, cudaFuncAttributeMaxDynamicSharedMemorySize, G_SMEM);

    router_kernel<<<dim3(64, 2), 256>>>(x, gw, out);     // launch 0
    scan_kernel<<<1, 256>>>();                           // launch 1
    fill_kernel<<<4, 256>>>();                           // launch 2
    gemm1_kernel<<<dim3(6, 128), 256, G_SMEM>>>(gup);    // launch 3 (ncu target)
    gemm2_kernel<<<dim3(8, 128), 256, G_SMEM>>>(down, out);  // launch 4
}

// round 16
// speedup vs baseline: 1.6065x; 1.0610x over previous
#include <cuda_runtime.h>
#include <cuda.h>
#include <cuda_fp16.h>
#include <cstdint>
#include <cstddef>

#define T_TOK 1024
#define HDIM  2048
#define IDIM  768
#define NEXP  64
#define TOPK  4
#define MT    64      // m-tile (tokens per expert tile)

// ---------------- static device scratch (no allocations) ----------------
__device__ int      g_counts[NEXP];      // incremented by router, zeroed by scan
__device__ int      g_cnt2[NEXP];        // snapshot used by GEMMs
__device__ int      g_offs[NEXP];
__device__ int      g_cursor[NEXP];
__device__ int      g_topi[T_TOK * TOPK];
__device__ float    g_topw[T_TOK * TOPK];
__device__ int      g_tok[T_TOK * TOPK];
__device__ float    g_wt[T_TOK * TOPK];
__device__ int      g_work[160];
__device__ int      g_nwork;
__device__ __half   g_Xh[(size_t)T_TOK * HDIM];          // fp16 X, pair-permuted
__device__ __half   g_Yh[(size_t)T_TOK * TOPK * IDIM];   // fp16 Y, pair-permuted

// ---------------- helpers ----------------
__device__ __forceinline__ uint32_t f2h2(float lo, float hi) {
    uint32_t r;
    asm("cvt.rn.f16x2.f32 %0, %1, %2;" : "=r"(r) : "f"(hi), "f"(lo));
    return r;
}
__device__ __forceinline__ void mma16(float* c, const uint32_t* a, const uint32_t* b) {
    asm volatile(
        "mma.sync.aligned.m16n8k16.row.col.f32.f16.f16.f32 "
        "{%0,%1,%2,%3}, {%4,%5,%6,%7}, {%8,%9}, {%0,%1,%2,%3};"
        : "+f"(c[0]), "+f"(c[1]), "+f"(c[2]), "+f"(c[3])
        : "r"(a[0]), "r"(a[1]), "r"(a[2]), "r"(a[3]), "r"(b[0]), "r"(b[1]));
}
__device__ __forceinline__ void cp16(uint32_t dst_smem, const void* src) {
    asm volatile("cp.async.cg.shared.global [%0], [%1], 16;"
                 :: "r"(dst_smem), "l"(src));
}
__device__ __forceinline__ uint32_t smem_u32(const void* p) {
    uint32_t a;
    asm("{ .reg .u64 t; cvta.to.shared.u64 t, %1; cvt.u32.u64 %0, t; }"
        : "=r"(a) : "l"(p));
    return a;
}
#define CP_COMMIT()  asm volatile("cp.async.commit_group;")
#define CP_WAIT1()   asm volatile("cp.async.wait_group 1;")

__device__ __forceinline__ void tma3d(uint32_t dst, const CUtensorMap* tm,
                                      int x, int y, int z, uint32_t mbar) {
    asm volatile(
        "cp.async.bulk.tensor.3d.shared::cta.global.tile.mbarrier::complete_tx::bytes "
        "[%0], [%1, {%2, %3, %4}], [%5];"
        :: "r"(dst), "l"(tm), "r"(x), "r"(y), "r"(z), "r"(mbar) : "memory");
}
__device__ __forceinline__ void mbar_init(uint32_t mbar, uint32_t cnt) {
    asm volatile("mbarrier.init.shared.b64 [%0], %1;" :: "r"(mbar), "r"(cnt) : "memory");
}
__device__ __forceinline__ void mbar_expect_tx(uint32_t mbar, uint32_t bytes) {
    asm volatile("mbarrier.arrive.expect_tx.shared.b64 _, [%0], %1;"
                 :: "r"(mbar), "r"(bytes) : "memory");
}
__device__ __forceinline__ void mbar_wait(uint32_t mbar, uint32_t parity) {
    uint32_t done = 0;
    while (!done) {
        asm volatile(
            "{\n\t.reg .pred p;\n\t"
            "mbarrier.try_wait.parity.acquire.cta.shared::cta.b64 p, [%1], %2, 0x989680;\n\t"
            "selp.b32 %0, 1, 0, p;\n\t}"
            : "=r"(done) : "r"(mbar), "r"(parity) : "memory");
    }
}
// SW128 within a 128-B row: physical word = ((u ^ (r&7))<<2) | (w&3), u = w>>2
__device__ __forceinline__ const float* bswz(const char* Bst, int r, int w) {
    int phys = (((w >> 2) ^ (r & 7)) << 4) + ((w & 3) << 2);
    return (const float*)(Bst + r * 128 + phys);
}

// pair permutation in each 16-group: k -> (k&~15)|((k&7)>>1)<<2|((k>>3)&1)<<1|(k&1)

// ====== router: fp32 logits = X @ Gw^T + fused top-4; y=1: X->fp16 + zero out
__global__ __launch_bounds__(256) void router_kernel(const float* __restrict__ x,
                                                     const float* __restrict__ gw,
                                                     float* __restrict__ out) {
    const int tt = blockIdx.x;
    const int tid = threadIdx.x;

    if (blockIdx.y == 1) {
        float4 z = make_float4(0.f, 0.f, 0.f, 0.f);
        float4* o4 = (float4*)(out + (size_t)tt * 16 * HDIM);
        for (int i = tid; i < 16 * HDIM / 4; i += 256) o4[i] = z;
        for (int idx = tid; idx < 16 * (HDIM / 2); idx += 256) {
            int r = idx >> 10, k = (idx & (HDIM / 2 - 1)) * 2;
            const float* xr = x + (size_t)(tt * 16 + r) * HDIM;
            int p = (k & ~15) | (((k & 7) >> 1) << 2) | (((k >> 3) & 1) << 1);
            *(uint32_t*)&g_Xh[(size_t)(tt * 16 + r) * HDIM + p] = f2h2(xr[k], xr[k + 1]);
        }
        return;
    }

    __shared__ float Xs[16][72];
    __shared__ float Wt[64][72];
    const int t = tid & 15, eg = tid >> 4;
    float acc[4] = {0.f, 0.f, 0.f, 0.f};

    for (int kc = 0; kc < HDIM; kc += 64) {
        {
            int r = tid >> 4, q = tid & 15;
            float4 v = *(const float4*)(x + (size_t)(tt * 16 + r) * HDIM + kc + q * 4);
            *(float4*)&Xs[r][q * 4] = v;
        }
#pragma unroll
        for (int it = 0; it < 4; it++) {
            int s = it * 256 + tid;
            int e = s >> 4, q = s & 15;
            float4 v = *(const float4*)(gw + (size_t)e * HDIM + kc + q * 4);
            *(float4*)&Wt[e][q * 4] = v;
        }
        __syncthreads();
#pragma unroll
        for (int k = 0; k < 64; k += 4) {
            float4 a = *(const float4*)&Xs[t][k];
#pragma unroll
            for (int j = 0; j < 4; j++) {
                float4 b = *(const float4*)&Wt[eg * 4 + j][k];
                acc[j] += a.x * b.x + a.y * b.y + a.z * b.z + a.w * b.w;
            }
        }
        __syncthreads();
    }
#pragma unroll
    for (int j = 0; j < 4; j++) Wt[t][eg * 4 + j] = acc[j];
    __syncthreads();

    if (tid < 16) {
        float v0 = -1e30f, v1 = -1e30f, v2 = -1e30f, v3 = -1e30f;
        int i0 = 0, i1 = 0, i2 = 0, i3 = 0;
        for (int e = 0; e < NEXP; e++) {
            float l = Wt[tid][e];
            if (l > v3) {
                if (l > v2) {
                    v3 = v2; i3 = i2;
                    if (l > v1) {
                        v2 = v1; i2 = i1;
                        if (l > v0) { v1 = v0; i1 = i0; v0 = l; i0 = e; }
                        else        { v1 = l;  i1 = e; }
                    } else { v2 = l; i2 = e; }
                } else { v3 = l; i3 = e; }
            }
        }
        float e1 = expf(v1 - v0), e2 = expf(v2 - v0), e3 = expf(v3 - v0);
        float inv = 1.f / (1.f + e1 + e2 + e3);
        int   ii[4] = {i0, i1, i2, i3};
        float ww[4] = {inv, e1 * inv, e2 * inv, e3 * inv};
        int tok = tt * 16 + tid;
#pragma unroll
        for (int j = 0; j < TOPK; j++) {
            g_topi[tok * TOPK + j] = ii[j];
            g_topw[tok * TOPK + j] = ww[j];
            atomicAdd(&g_counts[ii[j]], 1);
        }
    }
}

// ------- scan: snapshot counts, offsets, work list; re-zero g_counts -------
__global__ __launch_bounds__(256) void scan_kernel() {
    __shared__ int cnt[NEXP], coff[NEXP], woff[NEXP];
    const int tid = threadIdx.x;
    if (tid < NEXP) {
        cnt[tid] = g_counts[tid];
        g_cnt2[tid] = cnt[tid];
        g_counts[tid] = 0;
    }
    __syncthreads();
    if (tid == 0) {
        int off = 0, w = 0;
        for (int i = 0; i < NEXP; i++) {
            coff[i] = off; off += cnt[i];
            woff[i] = w;   w += (cnt[i] + MT - 1) / MT;
        }
        g_nwork = w;
    }
    __syncthreads();
    if (tid < NEXP) {
        g_offs[tid] = coff[tid];
        g_cursor[tid] = 0;
        const int tiles = (cnt[tid] + MT - 1) / MT;
        for (int mt = 0; mt < tiles; mt++) g_work[woff[tid] + mt] = (tid << 6) | mt;
    }
}

// ------- fill compact per-expert token/weight lists ------------------------
__global__ __launch_bounds__(256) void fill_kernel() {
    const int t = blockIdx.x * 256 + threadIdx.x;
    if (t >= T_TOK) return;
#pragma unroll
    for (int j = 0; j < TOPK; j++) {
        int e = g_topi[t * TOPK + j];
        int p = atomicAdd(&g_cursor[e], 1);
        int idx = g_offs[e] + p;
        g_tok[idx] = t;
        g_wt[idx]  = g_topw[t * TOPK + j];
    }
}

// SMEM layout (bytes), both GEMMs, 2 stages, 2 CTAs/SM:
//   mbar[2] @0,8
//   A stages: 2 x (64 rows x 96 B) @128          (fp16, stride 48 halves, cp.async)
//   B stages: 2 x (256 rows x 128 B) @13312      (fp32, SW128 via TMA; 1024-aligned)
//   s_tok @78848 (256 B), s_wt @79104 (256 B)
#define A_ST_B  6144
#define B_ST_B  32768
#define B_BASE  13312
#define TOK_B   78848
#define G_SMEM  79872
#define TXB     32768u

// ====== GEMM1: Yh[slot] = silu(Xh@Wg^T) * (Xh@Wu^T) * route_w =============
// 256 thr (8 warps), 2 CTAs/SM. C tile m64 x (gate128 + up128); warp: n16+n16.
// B via TMA (2 boxes/chunk), A via cp.async.
__global__ __launch_bounds__(256, 2) void gemm1_kernel(
        const __grid_constant__ CUtensorMap tmb) {
    extern __shared__ char smc[];
    const int widx = blockIdx.y;
    if (widx >= g_nwork) return;
    const int jt = blockIdx.x;                 // 0..5
    const int packed = g_work[widx];
    const int e = packed >> 6, mt = packed & 63;
    const int base = g_offs[e] + mt * MT;
    int m_cnt = g_cnt2[e] - mt * MT; if (m_cnt > MT) m_cnt = MT;

    int*   s_tok = (int*)(smc + TOK_B);
    float* s_wt  = (float*)(smc + TOK_B + 256);
    const int tid = threadIdx.x;
    const int w = tid >> 5, lane = tid & 31;
    const int lr = lane >> 2, lc = lane & 3;
    const uint32_t smb = smem_u32(smc);

    if (tid == 0) { mbar_init(smb, 1); mbar_init(smb + 8, 1); }
    if (tid < 64) {
        int tk = 0; float wt = 0.f;
        if (tid < m_cnt) { tk = g_tok[base + tid]; wt = g_wt[base + tid]; }
        s_tok[tid] = tk; s_wt[tid] = wt;
    }
    __syncthreads();

    // A via cp.async: thread -> row tid>>2, 16B group tid&3
    const int arow = tid >> 2, ag = tid & 3;
    const __half* xsrc = &g_Xh[(size_t)s_tok[arow] * HDIM + ag * 8];
    const uint32_t adst = smb + 128 + arow * 96 + ag * 16;

    const int NC = HDIM / 32;   // 64 chunks
    // prologue: chunks 0,1
#pragma unroll
    for (int p = 0; p < 2; p++) {
        if (tid == 0) {
            mbar_expect_tx(smb + 8 * p, TXB);
            tma3d(smb + B_BASE + p * B_ST_B,         &tmb, p * 32, jt * 128,        e, smb + 8 * p);
            tma3d(smb + B_BASE + p * B_ST_B + 16384, &tmb, p * 32, IDIM + jt * 128, e, smb + 8 * p);
        }
        cp16(adst + p * A_ST_B, xsrc + p * 32);
        CP_COMMIT();
    }

    float cg[4][2][4], cu[4][2][4];
#pragma unroll
    for (int a = 0; a < 4; a++)
#pragma unroll
        for (int b = 0; b < 2; b++)
#pragma unroll
            for (int c = 0; c < 4; c++) { cg[a][b][c] = 0.f; cu[a][b][c] = 0.f; }

    for (int ck = 0; ck < NC; ck++) {
        const int st = ck & 1;
        mbar_wait(smb + 8 * st, (uint32_t)((ck >> 1) & 1));
        CP_WAIT1();
        __syncthreads();
        const __half* Ast = (const __half*)(smc + 128 + st * A_ST_B);
        const char*   Bst = smc + B_BASE + st * B_ST_B;
#pragma unroll
        for (int kki = 0; kki < 2; kki++) {
            const int kk = kki * 16;
            uint32_t a[4][4];
#pragma unroll
            for (int mi = 0; mi < 4; mi++) {
                uint2 lo = *(const uint2*)(Ast + (mi * 16 + lr) * 48 + kk + 4 * lc);
                uint2 hi = *(const uint2*)(Ast + (mi * 16 + 8 + lr) * 48 + kk + 4 * lc);
                a[mi][0] = lo.x; a[mi][1] = hi.x; a[mi][2] = lo.y; a[mi][3] = hi.y;
            }
            uint32_t bg[2][2], bu[2][2];
#pragma unroll
            for (int ni = 0; ni < 2; ni++) {
                int nr = w * 16 + ni * 8 + lr;
                float2 p0 = *(const float2*)bswz(Bst, nr, kk + 2 * lc);
                float2 p1 = *(const float2*)bswz(Bst, nr, kk + 2 * lc + 8);
                bg[ni][0] = f2h2(p0.x, p0.y); bg[ni][1] = f2h2(p1.x, p1.y);
                float2 q0 = *(const float2*)bswz(Bst, 128 + nr, kk + 2 * lc);
                float2 q1 = *(const float2*)bswz(Bst, 128 + nr, kk + 2 * lc + 8);
                bu[ni][0] = f2h2(q0.x, q0.y); bu[ni][1] = f2h2(q1.x, q1.y);
            }
#pragma unroll
            for (int mi = 0; mi < 4; mi++)
#pragma unroll
                for (int ni = 0; ni < 2; ni++) {
                    mma16(cg[mi][ni], a[mi], bg[ni]);
                    mma16(cu[mi][ni], a[mi], bu[ni]);
                }
        }
        __syncthreads();
        const int nk = ck + 2;
        if (nk < NC) {
            const int kc = nk * 32;
            if (tid == 0) {
                mbar_expect_tx(smb + 8 * st, TXB);
                tma3d(smb + B_BASE + st * B_ST_B,         &tmb, kc, jt * 128,        e, smb + 8 * st);
                tma3d(smb + B_BASE + st * B_ST_B + 16384, &tmb, kc, IDIM + jt * 128, e, smb + 8 * st);
            }
            cp16(adst + st * A_ST_B, xsrc + kc);
        }
        CP_COMMIT();
    }

    // epilogue: silu(g)*u*route_w -> Yh (fp16, pair-permuted)
#pragma unroll
    for (int mi = 0; mi < 4; mi++)
#pragma unroll
        for (int ni = 0; ni < 2; ni++) {
            const int n0 = jt * 128 + w * 16 + ni * 8 + 2 * lc;   // even
            const int p = (n0 & ~15) | (((n0 & 7) >> 1) << 2) | (((n0 >> 3) & 1) << 1);
#pragma unroll
            for (int h = 0; h < 2; h++) {
                int row = mi * 16 + lr + h * 8;
                if (row < m_cnt) {
                    float wt = s_wt[row];
                    float g0 = cg[mi][ni][h * 2],     g1 = cg[mi][ni][h * 2 + 1];
                    float u0 = cu[mi][ni][h * 2],     u1 = cu[mi][ni][h * 2 + 1];
                    float y0 = g0 / (1.f + __expf(-g0)) * u0 * wt;
                    float y1 = g1 / (1.f + __expf(-g1)) * u1 * wt;
                    *(uint32_t*)&g_Yh[(size_t)(base + row) * IDIM + p] = f2h2(y0, y1);
                }
            }
        }
}

// ====== GEMM2: out[token] += Yh @ W2^T (atomic combine), m64 x n256 =======
__global__ __launch_bounds__(256, 2) void gemm2_kernel(
        const __grid_constant__ CUtensorMap tmb, float* __restrict__ out) {
    extern __shared__ char smc[];
    const int widx = blockIdx.y;
    if (widx >= g_nwork) return;
    const int ht = blockIdx.x;                 // 0..7
    const int packed = g_work[widx];
    const int e = packed >> 6, mt = packed & 63;
    const int base = g_offs[e] + mt * MT;
    int m_cnt = g_cnt2[e] - mt * MT; if (m_cnt > MT) m_cnt = MT;

    const int tid = threadIdx.x;
    const int w = tid >> 5, lane = tid & 31;
    const int lr = lane >> 2, lc = lane & 3;
    const uint32_t smb = smem_u32(smc);

    if (tid == 0) { mbar_init(smb, 1); mbar_init(smb + 8, 1); }
    __syncthreads();

    const int arow = tid >> 2, ag = tid & 3;
    int slot = base + arow; if (slot > T_TOK * TOPK - 1) slot = T_TOK * TOPK - 1;
    const __half* ysrc = &g_Yh[(size_t)slot * IDIM + ag * 8];
    const uint32_t adst = smb + 128 + arow * 96 + ag * 16;

    const int NC = IDIM / 32;   // 24 chunks
#pragma unroll
    for (int p = 0; p < 2; p++) {
        if (tid == 0) {
            mbar_expect_tx(smb + 8 * p, TXB);
            tma3d(smb + B_BASE + p * B_ST_B, &tmb, p * 32, ht * 256, e, smb + 8 * p);
        }
        cp16(adst + p * A_ST_B, ysrc + p * 32);
        CP_COMMIT();
    }

    float c[4][4][4];
#pragma unroll
    for (int a = 0; a < 4; a++)
#pragma unroll
        for (int b = 0; b < 4; b++)
#pragma unroll
            for (int k = 0; k < 4; k++) c[a][b][k] = 0.f;

    for (int ck = 0; ck < NC; ck++) {
        const int st = ck & 1;
        mbar_wait(smb + 8 * st, (uint32_t)((ck >> 1) & 1));
        CP_WAIT1();
        __syncthreads();
        const __half* Ast = (const __half*)(smc + 128 + st * A_ST_B);
        const char*   Bst = smc + B_BASE + st * B_ST_B;
#pragma unroll
        for (int kki = 0; kki < 2; kki++) {
            const int kk = kki * 16;
            uint32_t a[4][4];
#pragma unroll
            for (int mi = 0; mi < 4; mi++) {
                uint2 lo = *(const uint2*)(Ast + (mi * 16 + lr) * 48 + kk + 4 * lc);
                uint2 hi = *(const uint2*)(Ast + (mi * 16 + 8 + lr) * 48 + kk + 4 * lc);
                a[mi][0] = lo.x; a[mi][1] = hi.x; a[mi][2] = lo.y; a[mi][3] = hi.y;
            }
            uint32_t b[4][2];
#pragma unroll
            for (int ni = 0; ni < 4; ni++) {
                int nr = w * 32 + ni * 8 + lr;
                float2 p0 = *(const float2*)bswz(Bst, nr, kk + 2 * lc);
                float2 p1 = *(const float2*)bswz(Bst, nr, kk + 2 * lc + 8);
                b[ni][0] = f2h2(p0.x, p0.y); b[ni][1] = f2h2(p1.x, p1.y);
            }
#pragma unroll
            for (int mi = 0; mi < 4; mi++)
#pragma unroll
                for (int ni = 0; ni < 4; ni++) mma16(c[mi][ni], a[mi], b[ni]);
        }
        __syncthreads();
        const int nk = ck + 2;
        if (nk < NC) {
            const int kc = nk * 32;
            if (tid == 0) {
                mbar_expect_tx(smb + 8 * st, TXB);
                tma3d(smb + B_BASE + st * B_ST_B, &tmb, kc, ht * 256, e, smb + 8 * st);
            }
            cp16(adst + st * A_ST_B, ysrc + kc);
        }
        CP_COMMIT();
    }

    // epilogue: atomic accumulate into out[token]
#pragma unroll
    for (int mi = 0; mi < 4; mi++) {
        int tok_h[2]; bool act[2];
#pragma unroll
        for (int h = 0; h < 2; h++) {
            int row = mi * 16 + lr + h * 8;
            act[h] = row < m_cnt;
            tok_h[h] = act[h] ? g_tok[base + row] : 0;
        }
#pragma unroll
        for (int ni = 0; ni < 4; ni++) {
            int col = ht * 256 + w * 32 + ni * 8 + 2 * lc;
#pragma unroll
            for (int h = 0; h < 2; h++) {
                if (act[h]) {
                    float* o = out + (size_t)tok_h[h] * HDIM + col;
                    atomicAdd(o,     c[mi][ni][h * 2]);
                    atomicAdd(o + 1, c[mi][ni][h * 2 + 1]);
                }
            }
        }
    }
}

// ---------------- launch ----------------
typedef CUresult (*EncodeFn)(CUtensorMap*, CUtensorMapDataType, cuuint32_t, void*,
                             const cuuint64_t*, const cuuint64_t*, const cuuint32_t*,
                             const cuuint32_t*, CUtensorMapInterleave, CUtensorMapSwizzle,
                             CUtensorMapL2promotion, CUtensorMapFloatOOBfill);

extern "C" void kernel_launch(void* const* d_in, const int* in_sizes, int n_in,
                              void* d_out, int out_size) {
    const float* x    = (const float*)d_in[0];   // [1,1024,2048]
    const float* gw   = (const float*)d_in[1];   // [64,2048]
    const float* gup  = (const float*)d_in[2];   // [64,1536,2048]
    const float* down = (const float*)d_in[3];   // [64,2048,768]
    float* out = (float*)d_out;

    // driver entry point via runtime (no -lcuda link dependency)
    EncodeFn enc = nullptr;
    cudaDriverEntryPointQueryResult qr;
    cudaGetDriverEntryPoint("cuTensorMapEncodeTiled", (void**)&enc,
                            cudaEnableDefault, &qr);

    CUtensorMap tm1{}, tm2{};
    {
        cuuint64_t dims[3]    = {HDIM, 2 * IDIM, NEXP};
        cuuint64_t strides[2] = {(cuuint64_t)HDIM * 4, (cuuint64_t)2 * IDIM * HDIM * 4};
        cuuint32_t box[3]     = {32, 128, 1};
        cuuint32_t es[3]      = {1, 1, 1};
        enc(&tm1, CU_TENSOR_MAP_DATA_TYPE_FLOAT32, 3, (void*)gup, dims, strides, box, es,
            CU_TENSOR_MAP_INTERLEAVE_NONE, CU_TENSOR_MAP_SWIZZLE_128B,
            CU_TENSOR_MAP_L2_PROMOTION_L2_128B, CU_TENSOR_MAP_FLOAT_OOB_FILL_NONE);
    }
    {
        cuuint64_t dims[3]    = {IDIM, HDIM, NEXP};
        cuuint64_t strides[2] = {(cuuint64_t)IDIM * 4, (cuuint64_t)HDIM * IDIM * 4};
        cuuint32_t box[3]     = {32, 256, 1};
        cuuint32_t es[3]      = {1, 1, 1};
        enc(&tm2, CU_TENSOR_MAP_DATA_TYPE_FLOAT32, 3, (void*)down, dims, strides, box, es,
            CU_TENSOR_MAP_INTERLEAVE_NONE, CU_TENSOR_MAP_SWIZZLE_128B,
            CU_TENSOR_MAP_L2_PROMOTION_L2_128B, CU_TENSOR_MAP_FLOAT_OOB_FILL_NONE);
    }

    cudaFuncSetAttribute(gemm1_kernel, cudaFuncAttributeMaxDynamicSharedMemorySize, G_SMEM);
    cudaFuncSetAttribute(gemm2_kernel, cudaFuncAttributeMaxDynamicSharedMemorySize, G_SMEM);

    router_kernel<<<dim3(64, 2), 256>>>(x, gw, out);       // launch 0
    scan_kernel<<<1, 256>>>();                             // launch 1
    fill_kernel<<<4, 256>>>();                             // launch 2
    gemm1_kernel<<<dim3(6, 128), 256, G_SMEM>>>(tm1);      // launch 3 (ncu target)
    gemm2_kernel<<<dim3(8, 128), 256, G_SMEM>>>(tm2, out); // launch 4
}